// round 16
// baseline (speedup 1.0000x reference)
#include <cuda_runtime.h>
#include <cuda_fp16.h>
#include <math.h>
#include <stdint.h>

#define Bn 512
#define Tn 512
#define NBLK 512          // 8 batch groups x 64 gate slices (8 units each)
#define NTHR 128
#define GRP 64            // CTAs per barrier group

// ---- dynamic SMEM layout (bytes) ----
#define OFF_H(b)   ((b) * 8192)             // 2 h chunk bufs (fp16): 64 rows x 128B (SW128)
#define OFF_W      16384                    // W tile (fp16): 512 k-rows x 64B (SW64) = 32KB
#define OFF_WIH    49152                    // 32 floats
#define OFF_BIAS   49280                    // 32 floats
#define SMEM_BYTES 49408                    // x4 CTAs = 198KB/SM < 228KB
// epilogue bounce regions (reuse buf0, free at that point)
#define BOUNCE_HH  0                        // 64x8 fp16 = 1KB
#define BOUNCE_HF  4096                     // 64x8 f32 = 2KB (final step only)

static __device__ __forceinline__ uint32_t sw128(uint32_t x) { return x ^ ((x >> 3) & 0x70); }
static __device__ __forceinline__ uint32_t sw64(uint32_t x)  { return x ^ ((x >> 3) & 0x30); }

// ---- global scratch (no cudaMalloc allowed) ----
__device__ __half g_hh[2][Bn][512];          // h (fp16), ping-pong, [batch][hidden]
__device__ float g_seqT[Tn][Bn];
__device__ float g_hf[Bn][512];              // final fp32 h for MLP head
__device__ unsigned g_icount = 0;            // one-time global init barrier
__device__ volatile unsigned g_igen = 0;
__device__ unsigned g_gcount[8][32];         // per-group counters (128B apart)
__device__ volatile unsigned g_ggen[8][32];  // per-group release gens

__device__ __forceinline__ uint32_t smem_u32(const void* p) {
    uint32_t a;
    asm("{ .reg .u64 t; cvta.to.shared.u64 t, %1; cvt.u32.u64 %0, t; }" : "=r"(a) : "l"(p));
    return a;
}
__device__ __forceinline__ void ldsm_x4(uint32_t* r, uint32_t addr) {
    asm volatile("ldmatrix.sync.aligned.m8n8.x4.shared.b16 {%0,%1,%2,%3}, [%4];"
                 : "=r"(r[0]), "=r"(r[1]), "=r"(r[2]), "=r"(r[3]) : "r"(addr));
}
__device__ __forceinline__ void ldsm_x4_t(uint32_t* r, uint32_t addr) {
    asm volatile("ldmatrix.sync.aligned.m8n8.x4.trans.shared.b16 {%0,%1,%2,%3}, [%4];"
                 : "=r"(r[0]), "=r"(r[1]), "=r"(r[2]), "=r"(r[3]) : "r"(addr));
}
__device__ __forceinline__ void mma_f16(float* d, const uint32_t* a, const uint32_t* b) {
    asm volatile(
        "mma.sync.aligned.m16n8k16.row.col.f32.f16.f16.f32 "
        "{%0,%1,%2,%3}, {%4,%5,%6,%7}, {%8,%9}, {%0,%1,%2,%3};"
        : "+f"(d[0]), "+f"(d[1]), "+f"(d[2]), "+f"(d[3])
        : "r"(a[0]), "r"(a[1]), "r"(a[2]), "r"(a[3]), "r"(b[0]), "r"(b[1]));
}
__device__ __forceinline__ void cp16(uint32_t dst, const void* src) {
    asm volatile("cp.async.cg.shared.global [%0], [%1], 16;"
                 :: "r"(dst), "l"(__cvta_generic_to_global(src)) : "memory");
}
__device__ __forceinline__ void cp_commit() {
    asm volatile("cp.async.commit_group;" ::: "memory");
}
__device__ __forceinline__ void cp_wait0() {
    asm volatile("cp.async.wait_group 0;" ::: "memory");
}

// One-time global barrier across all 512 CTAs (init data visibility).
__device__ __forceinline__ void init_sync(unsigned target) {
    __syncthreads();
    if (threadIdx.x == 0) {
        __threadfence();
        unsigned old = atomicAdd(&g_icount, 1u);
        if (old == NBLK - 1) {
            g_icount = 0;
            __threadfence();
            g_igen = target;
        } else {
            while (g_igen != target) { }
            __threadfence();
        }
    }
    __syncthreads();
}

// Per-batch-group barrier (64 CTAs) — groups independent between steps.
__device__ __forceinline__ void group_sync(unsigned target, int grp) {
    __syncthreads();
    if (threadIdx.x == 0) {
        __threadfence();
        unsigned old = atomicAdd(&g_gcount[grp][0], 1u);
        if (old == GRP - 1) {
            g_gcount[grp][0] = 0;
            __threadfence();
            g_ggen[grp][0] = target;
        } else {
            while (g_ggen[grp][0] != target) { }
            __threadfence();
        }
    }
    __syncthreads();
}

// Exact sigmoid (EX2-based); tanh.approx only on the additive path (R10-validated).
__device__ __forceinline__ float sigf(float x)  { return __fdividef(1.0f, 1.0f + __expf(-x)); }
__device__ __forceinline__ float tanh_ap(float x) {
    float y;
    asm("tanh.approx.f32 %0, %1;" : "=f"(y) : "f"(x));
    return y;
}

__global__ __launch_bounds__(NTHR, 4)
void lstm_tc(const float* __restrict__ seq,
             const float* __restrict__ Wih,
             const float* __restrict__ Whh,
             const float* __restrict__ bih,
             const float* __restrict__ bhh)
{
    extern __shared__ char smem[];
    __shared__ unsigned s_ibase, s_gbase;
    const uint32_t sb = smem_u32(smem);
    const int tid  = threadIdx.x;
    const int w    = tid >> 5;
    const int lane = tid & 31;
    const int bi   = blockIdx.x >> 6;   // batch group 0..7 (64 rows each)
    const int ji   = blockIdx.x & 63;   // gate slice 0..63 (8 units each)
    const int b0   = bi * 64;
    const int j0   = ji * 8;

    if (tid == 0) { s_ibase = g_igen; s_gbase = g_ggen[bi][0]; }

    // ---- W_hh tile -> SMEM, fp16, k-major [k][n], 64B rows, SW64 swizzle ----
    // local col n = jl*4+g (jl 0..7) <-> global W row = g*512 + j0 + jl
    for (int idx = tid; idx < 32 * 512; idx += NTHR) {
        int n = idx >> 9, k = idx & 511;
        int row = (n & 3) * 512 + j0 + (n >> 2);
        float wv = Whh[(size_t)row * 512 + k];
        uint32_t so = sw64((uint32_t)k * 64 + n * 2);
        *(__half*)(smem + OFF_W + so) = __float2half_rn(wv);
    }
    if (tid < 32) {
        int jl = tid >> 2, g = tid & 3;
        int row = g * 512 + j0 + jl;
        ((float*)(smem + OFF_WIH))[tid]  = Wih[row];
        ((float*)(smem + OFF_BIAS))[tid] = bih[row] + bhh[row];
    }
    // zero h0 (buffer 0) and transpose sequence (global coverage -> global init barrier)
    {
        int base = blockIdx.x * 512;
        #pragma unroll
        for (int i = 0; i < 4; ++i) {
            int idx = base + i * NTHR + tid;
            ((__half*)g_hh)[idx] = __float2half_rn(0.0f);
            int b = idx >> 9, t = idx & 511;
            g_seqT[t][b] = seq[idx];
        }
    }
    init_sync(s_ibase + 1);
    const unsigned gbase = s_gbase;

    // ---- per-lane constants (4 warps: warp tile m16 x n32 over 64x32 D tile) ----
    const int wm = w;                    // m16 quarter (0..3)
    const int l15 = lane & 15;
    const int lb  = lane >> 4;
    const uint32_t a_row  = (uint32_t)(wm * 16 + l15);
    const uint32_t a_xm   = a_row & 7;
    const uint32_t a_base = sb + a_row * 128;
    // B (SW64, 64B rows): 16B-block index = n8-block ^ ((k>>1)&3); all OFFSET-level math.
    const uint32_t b_base_a = sb + OFF_W + (uint32_t)l15 * 64
                              + ((uint32_t)((lb)     ^ ((l15 >> 1) & 3)) << 4);
    const uint32_t b_base_b = sb + OFF_W + (uint32_t)l15 * 64
                              + ((uint32_t)((2 + lb) ^ ((l15 >> 1) & 3)) << 4);

    // staging (cp.async dst): 128 threads, each copies 64B: row tid>>1 (0..63), half tid&1
    const int sm_r = tid >> 1, shf = tid & 1;
    const uint32_t sts_off = sw128((uint32_t)sm_r * 128 + shf * 64);
    // raw offset bits 4..5 are 0 -> sw128(x + {16,32,48}) == sw128(x) ^ {16,32,48} (offset-level)

    const float* wih_s  = (const float*)(smem + OFF_WIH);
    const float* bias_s = (const float*)(smem + OFF_BIAS);
    float bw_a[4], bw_b[4], wi_a[4], wi_b[4];
    #pragma unroll
    for (int nt = 0; nt < 4; ++nt) {
        int ca = nt * 8 + (lane & 3) * 2;
        bw_a[nt] = bias_s[ca];     bw_b[nt] = bias_s[ca + 1];
        wi_a[nt] = wih_s[ca];      wi_b[nt] = wih_s[ca + 1];
    }
    const int q = lane & 1;
    const int rowm0 = wm * 16 + (lane >> 2);
    float cst[4];
    #pragma unroll
    for (int i = 0; i < 4; ++i) cst[i] = 0.f;

    for (int t = 0; t < Tn; ++t) {
        const int rb = t & 1, nb = rb ^ 1;

        // init accumulators with bias + x*W_ih (mma accumulates on top)
        // acc[nt][0..3]: c0/c1 = row rowm0, c2/c3 = row rowm0+8
        float acc[4][4];
        {
            float svA = g_seqT[t][b0 + rowm0];
            float svB = g_seqT[t][b0 + rowm0 + 8];
            #pragma unroll
            for (int nt = 0; nt < 4; ++nt) {
                acc[nt][0] = fmaf(svA, wi_a[nt], bw_a[nt]);
                acc[nt][1] = fmaf(svA, wi_b[nt], bw_b[nt]);
                acc[nt][2] = fmaf(svB, wi_a[nt], bw_a[nt]);
                acc[nt][3] = fmaf(svB, wi_b[nt], bw_b[nt]);
            }
        }

        // stage chunk 0 into buf 0 (h visible after group barrier)
        {
            const __half* sh = &g_hh[rb][b0 + sm_r][shf * 32];
            cp16(sb + OFF_H(0) + sts_off,        sh);
            cp16(sb + OFF_H(0) + (sts_off ^ 16), sh + 8);
            cp16(sb + OFF_H(0) + (sts_off ^ 32), sh + 16);
            cp16(sb + OFF_H(0) + (sts_off ^ 48), sh + 24);
            cp_commit();
        }

        #pragma unroll 1
        for (int kc = 0; kc < 8; ++kc) {
            cp_wait0();
            __syncthreads();      // chunk kc visible; prior reads of other buf done
            if (kc < 7) {
                const int nbuf = (kc + 1) & 1;
                const __half* sh = &g_hh[rb][b0 + sm_r][(kc + 1) * 64 + shf * 32];
                cp16(sb + OFF_H(nbuf) + sts_off,        sh);
                cp16(sb + OFF_H(nbuf) + (sts_off ^ 16), sh + 8);
                cp16(sb + OFF_H(nbuf) + (sts_off ^ 32), sh + 16);
                cp16(sb + OFF_H(nbuf) + (sts_off ^ 48), sh + 24);
                cp_commit();
            }

            const uint32_t abuf = a_base + OFF_H(kc & 1);
            const uint32_t bka  = b_base_a + (uint32_t)kc * 4096;   // +64 k rows * 64B
            const uint32_t bkb  = b_base_b + (uint32_t)kc * 4096;
            #pragma unroll
            for (int kq = 0; kq < 4; ++kq) {
                const uint32_t acol = (uint32_t)(((kq * 2 + lb) ^ a_xm)) << 4;
                uint32_t a[4], b0r[4], b1r[4];
                ldsm_x4(a, abuf + acol);                          // A m16 k16
                ldsm_x4_t(b0r, bka + (uint32_t)kq * 1024);        // W k16 x n16 (cols 0..15)
                ldsm_x4_t(b1r, bkb + (uint32_t)kq * 1024);        // W k16 x n16 (cols 16..31)
                // 4 MMA per kq (3 LDSM)
                mma_f16(acc[0], a, b0r);  mma_f16(acc[1], a, b0r + 2);
                mma_f16(acc[2], a, b1r);  mma_f16(acc[3], a, b1r + 2);
            }
        }

        __syncthreads();   // all chunk reads done -> buf0 reusable as bounce

        // ---- LSTM cell epilogue: lane pairs exchange (i,f)<->(g,o) ----
        #pragma unroll
        for (int nt = 0; nt < 4; ++nt) {
            float x0 = __shfl_xor_sync(0xffffffffu, acc[nt][0], 1);
            float x1 = __shfl_xor_sync(0xffffffffu, acc[nt][1], 1);
            float x2 = __shfl_xor_sync(0xffffffffu, acc[nt][2], 1);
            float x3 = __shfl_xor_sync(0xffffffffu, acc[nt][3], 1);
            float gi, gf, gg, go;
            int rowl;
            if (q == 0) { gi = acc[nt][0]; gf = acc[nt][1]; gg = x0; go = x1;
                          rowl = rowm0; }
            else        { gi = x2; gf = x3; gg = acc[nt][2]; go = acc[nt][3];
                          rowl = rowm0 + 8; }
            cst[nt] = sigf(gf) * cst[nt] + sigf(gi) * tanh_ap(gg);
            float h = sigf(go) * tanh_ap(cst[nt]);
            int ul = nt * 2 + ((lane & 3) >> 1);   // local unit 0..7
            *(__half*)(smem + BOUNCE_HH + rowl * 16 + ul * 2) = __float2half_rn(h);
            if (t == Tn - 1)
                *(float*)(smem + BOUNCE_HF + rowl * 32 + ul * 4) = h;
        }
        __syncthreads();
        // coalesced write-out of this CTA's 64x8 h slice
        if (t < Tn - 1) {
            if (tid < 64) {
                uint4 hv = *(uint4*)(smem + BOUNCE_HH + tid * 16);
                *(uint4*)&g_hh[nb][b0 + tid][j0] = hv;
            }
        } else {
            float4 f0 = *(float4*)(smem + BOUNCE_HF + sm_r * 32 + shf * 16);
            *(float4*)&g_hf[b0 + sm_r][j0 + shf * 4] = f0;
        }
        group_sync(gbase + 1 + t, bi);
    }
}

__global__ __launch_bounds__(256)
void mlp_head(const float* __restrict__ fc1w, const float* __restrict__ fc1b,
              const float* __restrict__ fc2w, const float* __restrict__ fc2b,
              float* __restrict__ out)
{
    __shared__ float hcol[512];
    __shared__ float z[256];
    const int b = blockIdx.x;
    const int tid = threadIdx.x;

    hcol[tid]       = g_hf[b][tid];
    hcol[tid + 256] = g_hf[b][tid + 256];
    __syncthreads();

    float acc = fc1b[tid];
    const float4* w4 = (const float4*)(fc1w + (size_t)tid * 512);
    const float4* h4 = (const float4*)hcol;
    #pragma unroll 4
    for (int k = 0; k < 128; ++k) {
        float4 wv = w4[k], hv = h4[k];
        acc = fmaf(wv.x, hv.x, acc); acc = fmaf(wv.y, hv.y, acc);
        acc = fmaf(wv.z, hv.z, acc); acc = fmaf(wv.w, hv.w, acc);
    }
    z[tid] = fmaxf(acc, 0.0f);
    __syncthreads();

    if (tid < 28) {
        float o = fc2b[tid];
        const float4* w4b = (const float4*)(fc2w + (size_t)tid * 256);
        const float4* z4  = (const float4*)z;
        #pragma unroll 4
        for (int k = 0; k < 64; ++k) {
            float4 wv = w4b[k], zz = z4[k];
            o = fmaf(wv.x, zz.x, o); o = fmaf(wv.y, zz.y, o);
            o = fmaf(wv.z, zz.z, o); o = fmaf(wv.w, zz.w, o);
        }
        out[b * 28 + tid] = o;
    }
}

extern "C" void kernel_launch(void* const* d_in, const int* in_sizes, int n_in,
                              void* d_out, int out_size) {
    const float* seq  = (const float*)d_in[0];
    const float* Wih  = (const float*)d_in[1];
    const float* Whh  = (const float*)d_in[2];
    const float* bih  = (const float*)d_in[3];
    const float* bhh  = (const float*)d_in[4];
    const float* fc1w = (const float*)d_in[5];
    const float* fc1b = (const float*)d_in[6];
    const float* fc2w = (const float*)d_in[7];
    const float* fc2b = (const float*)d_in[8];
    float* out = (float*)d_out;

    cudaFuncSetAttribute(lstm_tc, cudaFuncAttributeMaxDynamicSharedMemorySize, SMEM_BYTES);
    lstm_tc<<<NBLK, NTHR, SMEM_BYTES>>>(seq, Wih, Whh, bih, bhh);
    mlp_head<<<Bn, 256>>>(fc1w, fc1b, fc2w, fc2b, out);
}

// round 17
// speedup vs baseline: 1.2270x; 1.2270x over previous
#include <cuda_runtime.h>
#include <cuda_fp16.h>
#include <math.h>
#include <stdint.h>

#define Bn 512
#define Tn 512
#define NBLK 256          // 8 batch groups x 32 gate slices
#define NTHR 128
#define GRP 32            // CTAs per barrier group

// ---- dynamic SMEM layout (bytes) ----
#define OFF_H(b)   ((b) * 16384)            // 2 h chunk bufs (fp16): k128 = two 64-k panels,
                                            // each panel 64 rows x 128B (SW128) = 8KB
#define OFF_W      32768                    // W tile (fp16): 512 k-rows x 128B (SW128) = 64KB
#define OFF_WIH    98304                    // 64 floats
#define OFF_BIAS   98560                    // 64 floats
#define SMEM_BYTES 98816                    // x2 CTAs = 197.6KB/SM < 228KB
// epilogue bounce regions (reuse buf0, free at that point)
#define BOUNCE_HH  0                        // 64x16 fp16 = 2KB
#define BOUNCE_HF  4096                     // 64x16 f32 = 4KB (final step only)

static __device__ __forceinline__ uint32_t sw128(uint32_t x) { return x ^ ((x >> 3) & 0x70); }

// ---- global scratch (no cudaMalloc allowed) ----
__device__ __half g_hh[2][Bn][512];          // h (fp16), ping-pong, [batch][hidden]
__device__ float g_seqT[Tn][Bn];
__device__ float g_hf[Bn][512];              // final fp32 h for MLP head
__device__ unsigned g_icount = 0;            // one-time global init barrier
__device__ volatile unsigned g_igen = 0;
__device__ unsigned g_gcount[8][32];         // per-group counters (128B apart)
__device__ volatile unsigned g_ggen[8][32];  // per-group release gens

__device__ __forceinline__ uint32_t smem_u32(const void* p) {
    uint32_t a;
    asm("{ .reg .u64 t; cvta.to.shared.u64 t, %1; cvt.u32.u64 %0, t; }" : "=r"(a) : "l"(p));
    return a;
}
__device__ __forceinline__ void ldsm_x4(uint32_t* r, uint32_t addr) {
    asm volatile("ldmatrix.sync.aligned.m8n8.x4.shared.b16 {%0,%1,%2,%3}, [%4];"
                 : "=r"(r[0]), "=r"(r[1]), "=r"(r[2]), "=r"(r[3]) : "r"(addr));
}
__device__ __forceinline__ void ldsm_x4_t(uint32_t* r, uint32_t addr) {
    asm volatile("ldmatrix.sync.aligned.m8n8.x4.trans.shared.b16 {%0,%1,%2,%3}, [%4];"
                 : "=r"(r[0]), "=r"(r[1]), "=r"(r[2]), "=r"(r[3]) : "r"(addr));
}
__device__ __forceinline__ void mma_f16(float* d, const uint32_t* a, const uint32_t* b) {
    asm volatile(
        "mma.sync.aligned.m16n8k16.row.col.f32.f16.f16.f32 "
        "{%0,%1,%2,%3}, {%4,%5,%6,%7}, {%8,%9}, {%0,%1,%2,%3};"
        : "+f"(d[0]), "+f"(d[1]), "+f"(d[2]), "+f"(d[3])
        : "r"(a[0]), "r"(a[1]), "r"(a[2]), "r"(a[3]), "r"(b[0]), "r"(b[1]));
}
__device__ __forceinline__ void cp16(uint32_t dst, const void* src) {
    asm volatile("cp.async.cg.shared.global [%0], [%1], 16;"
                 :: "r"(dst), "l"(__cvta_generic_to_global(src)) : "memory");
}
__device__ __forceinline__ void cp_commit() {
    asm volatile("cp.async.commit_group;" ::: "memory");
}
__device__ __forceinline__ void cp_wait0() {
    asm volatile("cp.async.wait_group 0;" ::: "memory");
}

// One-time global barrier across all 256 CTAs (init data visibility).
__device__ __forceinline__ void init_sync(unsigned target) {
    __syncthreads();
    if (threadIdx.x == 0) {
        __threadfence();
        unsigned old = atomicAdd(&g_icount, 1u);
        if (old == NBLK - 1) {
            g_icount = 0;
            __threadfence();
            g_igen = target;
        } else {
            while (g_igen != target) { }
            __threadfence();
        }
    }
    __syncthreads();
}

// Per-batch-group barrier (32 CTAs) — groups are independent between steps.
__device__ __forceinline__ void group_sync(unsigned target, int grp) {
    __syncthreads();
    if (threadIdx.x == 0) {
        __threadfence();
        unsigned old = atomicAdd(&g_gcount[grp][0], 1u);
        if (old == GRP - 1) {
            g_gcount[grp][0] = 0;
            __threadfence();
            g_ggen[grp][0] = target;
        } else {
            while (g_ggen[grp][0] != target) { }
            __threadfence();
        }
    }
    __syncthreads();
}

// f-gate: EXACT sigmoid (R11 lesson: f-gate bias compounds ~512x uncontracted).
__device__ __forceinline__ float sigf(float x)  { return __fdividef(1.0f, 1.0f + __expf(-x)); }
// i/o gates + additive path: fast approx (errors contract; tanh_ap R10-validated).
__device__ __forceinline__ float tanh_ap(float x) {
    float y;
    asm("tanh.approx.f32 %0, %1;" : "=f"(y) : "f"(x));
    return y;
}
__device__ __forceinline__ float sig_ap(float x) {
    return fmaf(tanh_ap(0.5f * x), 0.5f, 0.5f);
}

__global__ __launch_bounds__(NTHR, 2)
void lstm_tc(const float* __restrict__ seq,
             const float* __restrict__ Wih,
             const float* __restrict__ Whh,
             const float* __restrict__ bih,
             const float* __restrict__ bhh)
{
    extern __shared__ char smem[];
    __shared__ unsigned s_ibase, s_gbase;
    const uint32_t sb = smem_u32(smem);
    const int tid  = threadIdx.x;
    const int w    = tid >> 5;
    const int lane = tid & 31;
    const int bi   = blockIdx.x >> 5;   // batch group 0..7 (64 rows each)
    const int ji   = blockIdx.x & 31;   // hidden-slice tile 0..31 (16 units each)
    const int b0   = bi * 64;
    const int j0   = ji * 16;

    if (tid == 0) { s_ibase = g_igen; s_gbase = g_ggen[bi][0]; }

    // ---- W_hh tile -> SMEM, fp16, k-major [k][n], SW128 swizzle ----
    // local col n = jl*4+g  <->  global W row = g*512 + j0 + jl
    for (int idx = tid; idx < 64 * 512; idx += NTHR) {
        int n = idx >> 9, k = idx & 511;
        int row = (n & 3) * 512 + j0 + (n >> 2);
        float wv = Whh[(size_t)row * 512 + k];
        uint32_t so = sw128((uint32_t)k * 128 + n * 2);
        *(__half*)(smem + OFF_W + so) = __float2half_rn(wv);
    }
    if (tid < 64) {
        int jl = tid >> 2, g = tid & 3;
        int row = g * 512 + j0 + jl;
        ((float*)(smem + OFF_WIH))[tid]  = Wih[row];
        ((float*)(smem + OFF_BIAS))[tid] = bih[row] + bhh[row];
    }
    // zero h0 (buffer 0) and transpose sequence (global coverage -> global init barrier)
    {
        int base = blockIdx.x * 1024;
        #pragma unroll
        for (int i = 0; i < 8; ++i) {
            int idx = base + i * NTHR + tid;
            ((__half*)g_hh)[idx] = __float2half_rn(0.0f);
            int b = idx >> 9, t = idx & 511;
            g_seqT[t][b] = seq[idx];
        }
    }
    init_sync(s_ibase + 1);
    const unsigned gbase = s_gbase;

    // ---- per-lane constants (4 warps: warp tile m32 x n32 over 64x64 D tile) ----
    const int wm = w & 1;                // batch half (m32)
    const int wn = w >> 1;               // gate-col half (n32): 0 or 1
    const int l15 = lane & 15;
    const int lb  = lane >> 4;
    const uint32_t a_row  = (uint32_t)(wm * 32 + l15);
    const uint32_t a_xm   = a_row & 7;
    const uint32_t a_base = sb + a_row * 128;
    // B: two OFFSET-computed column bases (no address-level XOR — R11/R12 lesson).
    const uint32_t b_col16a = (uint32_t)(((wn * 4 + lb)     ^ (l15 & 7)));
    const uint32_t b_col16b = (uint32_t)(((wn * 4 + 2 + lb) ^ (l15 & 7)));
    const uint32_t b_base_a = sb + OFF_W + (uint32_t)l15 * 128 + b_col16a * 16;
    const uint32_t b_base_b = sb + OFF_W + (uint32_t)l15 * 128 + b_col16b * 16;

    // staging (cp.async dst): 128 threads, each copies 64B/panel: row tid>>1, half tid&1
    const int sm_r = tid >> 1, shf = tid & 1;
    const uint32_t sts_off = sw128((uint32_t)sm_r * 128 + shf * 64);
    // raw offset bits 4..5 are 0 -> sw128(x + {16,32,48}) == sw128(x) ^ {16,32,48} (offset-level)

    const float* wih_s  = (const float*)(smem + OFF_WIH);
    const float* bias_s = (const float*)(smem + OFF_BIAS);
    float bw_a[4], bw_b[4], wi_a[4], wi_b[4];
    #pragma unroll
    for (int nt = 0; nt < 4; ++nt) {
        int ca = wn * 32 + nt * 8 + (lane & 3) * 2;
        bw_a[nt] = bias_s[ca];     bw_b[nt] = bias_s[ca + 1];
        wi_a[nt] = wih_s[ca];      wi_b[nt] = wih_s[ca + 1];
    }
    const int q = lane & 1;
    const int rowm0 = wm * 32 + (lane >> 2);
    float cst[8];
    #pragma unroll
    for (int i = 0; i < 8; ++i) cst[i] = 0.f;

    for (int t = 0; t < Tn; ++t) {
        const int rb = t & 1, nb = rb ^ 1;

        // init accumulators with bias + x*W_ih (mma accumulates on top)
        float acc[2][4][4];
        #pragma unroll
        for (int mt = 0; mt < 2; ++mt) {
            float svA = g_seqT[t][b0 + rowm0 + mt * 16];
            float svB = g_seqT[t][b0 + rowm0 + mt * 16 + 8];
            #pragma unroll
            for (int nt = 0; nt < 4; ++nt) {
                acc[mt][nt][0] = fmaf(svA, wi_a[nt], bw_a[nt]);
                acc[mt][nt][1] = fmaf(svA, wi_b[nt], bw_b[nt]);
                acc[mt][nt][2] = fmaf(svB, wi_a[nt], bw_a[nt]);
                acc[mt][nt][3] = fmaf(svB, wi_b[nt], bw_b[nt]);
            }
        }

        // stage chunk 0 (k128 = 2 panels) into buf 0 (h visible after group barrier)
        {
            const __half* sh = &g_hh[rb][b0 + sm_r][shf * 32];
            cp16(sb + OFF_H(0) + sts_off,        sh);
            cp16(sb + OFF_H(0) + (sts_off ^ 16), sh + 8);
            cp16(sb + OFF_H(0) + (sts_off ^ 32), sh + 16);
            cp16(sb + OFF_H(0) + (sts_off ^ 48), sh + 24);
            const __half* s2 = sh + 64;
            cp16(sb + OFF_H(0) + 8192 + sts_off,        s2);
            cp16(sb + OFF_H(0) + 8192 + (sts_off ^ 16), s2 + 8);
            cp16(sb + OFF_H(0) + 8192 + (sts_off ^ 32), s2 + 16);
            cp16(sb + OFF_H(0) + 8192 + (sts_off ^ 48), s2 + 24);
            cp_commit();
        }

        #pragma unroll 1
        for (int kc = 0; kc < 4; ++kc) {
            cp_wait0();
            __syncthreads();      // chunk kc visible; prior reads of other buf done
            if (kc < 3) {
                const int nbuf = (kc + 1) & 1;
                const __half* sh = &g_hh[rb][b0 + sm_r][(kc + 1) * 128 + shf * 32];
                cp16(sb + OFF_H(nbuf) + sts_off,        sh);
                cp16(sb + OFF_H(nbuf) + (sts_off ^ 16), sh + 8);
                cp16(sb + OFF_H(nbuf) + (sts_off ^ 32), sh + 16);
                cp16(sb + OFF_H(nbuf) + (sts_off ^ 48), sh + 24);
                const __half* s2 = sh + 64;
                cp16(sb + OFF_H(nbuf) + 8192 + sts_off,        s2);
                cp16(sb + OFF_H(nbuf) + 8192 + (sts_off ^ 16), s2 + 8);
                cp16(sb + OFF_H(nbuf) + 8192 + (sts_off ^ 32), s2 + 16);
                cp16(sb + OFF_H(nbuf) + 8192 + (sts_off ^ 48), s2 + 24);
                cp_commit();
            }

            const uint32_t abuf = a_base + OFF_H(kc & 1);
            const uint32_t bka  = b_base_a + (uint32_t)kc * 16384;   // +128 k rows * 128B
            const uint32_t bkb  = b_base_b + (uint32_t)kc * 16384;
            #pragma unroll
            for (int kq = 0; kq < 8; ++kq) {
                const uint32_t apan = abuf + (uint32_t)(kq >> 2) * 8192;
                const uint32_t acol = (uint32_t)((((kq & 3) * 2 + lb) ^ a_xm)) << 4;
                uint32_t ah0[4], ah1[4], b0r[4], b1r[4];
                ldsm_x4(ah0, apan + acol);                        // A m16 #0, k16
                ldsm_x4(ah1, apan + 2048 + acol);                 // A m16 #1
                ldsm_x4_t(b0r, bka + (uint32_t)kq * 2048);        // W k16 x n16 (cols 0..15)
                ldsm_x4_t(b1r, bkb + (uint32_t)kq * 2048);        // W k16 x n16 (cols 16..31)
                // 8 HMMA per kq
                mma_f16(acc[0][0], ah0, b0r);  mma_f16(acc[0][1], ah0, b0r + 2);
                mma_f16(acc[0][2], ah0, b1r);  mma_f16(acc[0][3], ah0, b1r + 2);
                mma_f16(acc[1][0], ah1, b0r);  mma_f16(acc[1][1], ah1, b0r + 2);
                mma_f16(acc[1][2], ah1, b1r);  mma_f16(acc[1][3], ah1, b1r + 2);
            }
        }

        __syncthreads();   // all chunk reads done -> buf0 reusable as bounce

        // ---- LSTM cell epilogue: lane pairs exchange (i,f)<->(g,o) ----
        #pragma unroll
        for (int mt = 0; mt < 2; ++mt) {
            #pragma unroll
            for (int nt = 0; nt < 4; ++nt) {
                float x0 = __shfl_xor_sync(0xffffffffu, acc[mt][nt][0], 1);
                float x1 = __shfl_xor_sync(0xffffffffu, acc[mt][nt][1], 1);
                float x2 = __shfl_xor_sync(0xffffffffu, acc[mt][nt][2], 1);
                float x3 = __shfl_xor_sync(0xffffffffu, acc[mt][nt][3], 1);
                float gi, gf, gg, go;
                int rowl;
                if (q == 0) { gi = acc[mt][nt][0]; gf = acc[mt][nt][1]; gg = x0; go = x1;
                              rowl = rowm0 + mt * 16; }
                else        { gi = x2; gf = x3; gg = acc[mt][nt][2]; go = acc[mt][nt][3];
                              rowl = rowm0 + mt * 16 + 8; }
                const int ci = mt * 4 + nt;
                cst[ci] = sigf(gf) * cst[ci] + sig_ap(gi) * tanh_ap(gg);
                float h = sig_ap(go) * tanh_ap(cst[ci]);
                int ul = wn * 8 + nt * 2 + ((lane & 3) >> 1);   // local unit 0..15
                *(__half*)(smem + BOUNCE_HH + rowl * 32 + ul * 2) = __float2half_rn(h);
                if (t == Tn - 1)
                    *(float*)(smem + BOUNCE_HF + rowl * 64 + ul * 4) = h;
            }
        }
        __syncthreads();
        // coalesced write-out of this CTA's 64x16 h slice (128 thr: 16B each)
        if (t < Tn - 1) {
            uint4 hv = *(uint4*)(smem + BOUNCE_HH + sm_r * 32 + shf * 16);
            *(uint4*)&g_hh[nb][b0 + sm_r][j0 + shf * 8] = hv;
        } else {
            float4 f0 = *(float4*)(smem + BOUNCE_HF + sm_r * 64 + shf * 32);
            float4 f1 = *(float4*)(smem + BOUNCE_HF + sm_r * 64 + shf * 32 + 16);
            *(float4*)&g_hf[b0 + sm_r][j0 + shf * 8]     = f0;
            *(float4*)&g_hf[b0 + sm_r][j0 + shf * 8 + 4] = f1;
        }
        group_sync(gbase + 1 + t, bi);
    }
}

__global__ __launch_bounds__(256)
void mlp_head(const float* __restrict__ fc1w, const float* __restrict__ fc1b,
              const float* __restrict__ fc2w, const float* __restrict__ fc2b,
              float* __restrict__ out)
{
    __shared__ float hcol[512];
    __shared__ float z[256];
    const int b = blockIdx.x;
    const int tid = threadIdx.x;

    hcol[tid]       = g_hf[b][tid];
    hcol[tid + 256] = g_hf[b][tid + 256];
    __syncthreads();

    float acc = fc1b[tid];
    const float4* w4 = (const float4*)(fc1w + (size_t)tid * 512);
    const float4* h4 = (const float4*)hcol;
    #pragma unroll 4
    for (int k = 0; k < 128; ++k) {
        float4 wv = w4[k], hv = h4[k];
        acc = fmaf(wv.x, hv.x, acc); acc = fmaf(wv.y, hv.y, acc);
        acc = fmaf(wv.z, hv.z, acc); acc = fmaf(wv.w, hv.w, acc);
    }
    z[tid] = fmaxf(acc, 0.0f);
    __syncthreads();

    if (tid < 28) {
        float o = fc2b[tid];
        const float4* w4b = (const float4*)(fc2w + (size_t)tid * 256);
        const float4* z4  = (const float4*)z;
        #pragma unroll 4
        for (int k = 0; k < 64; ++k) {
            float4 wv = w4b[k], zz = z4[k];
            o = fmaf(wv.x, zz.x, o); o = fmaf(wv.y, zz.y, o);
            o = fmaf(wv.z, zz.z, o); o = fmaf(wv.w, zz.w, o);
        }
        out[b * 28 + tid] = o;
    }
}

extern "C" void kernel_launch(void* const* d_in, const int* in_sizes, int n_in,
                              void* d_out, int out_size) {
    const float* seq  = (const float*)d_in[0];
    const float* Wih  = (const float*)d_in[1];
    const float* Whh  = (const float*)d_in[2];
    const float* bih  = (const float*)d_in[3];
    const float* bhh  = (const float*)d_in[4];
    const float* fc1w = (const float*)d_in[5];
    const float* fc1b = (const float*)d_in[6];
    const float* fc2w = (const float*)d_in[7];
    const float* fc2b = (const float*)d_in[8];
    float* out = (float*)d_out;

    cudaFuncSetAttribute(lstm_tc, cudaFuncAttributeMaxDynamicSharedMemorySize, SMEM_BYTES);
    lstm_tc<<<NBLK, NTHR, SMEM_BYTES>>>(seq, Wih, Whh, bih, bhh);
    mlp_head<<<Bn, 256>>>(fc1w, fc1b, fc2w, fc2b, out);
}